// round 1
// baseline (speedup 1.0000x reference)
#include <cuda_runtime.h>

#define NB   32
#define NC   2
#define PP   262144          // H*W
#define BINS 65536
#define ROWS (NC * NB)       // 64 rows, row = c*NB + n
#define P2T  1024
#define SEG  (BINS / P2T)    // 64 bins per thread

// Scratch (static device globals; no allocation)
__device__ unsigned int g_hist[(size_t)ROWS * BINS];  // packed: hi16 = count(m=1), lo16 = count(m=0)
__device__ int          g_npred[ROWS];                // count of x > 0.25 per row
__device__ float        g_per[ROWS];
__device__ unsigned int g_gts[ROWS];

// ---------------------------------------------------------------- zero scratch
__global__ void __launch_bounds__(256) k_zero() {
  size_t i = (size_t)blockIdx.x * 256 + threadIdx.x;
  if (i < ((size_t)ROWS * BINS) / 4)
    ((uint4*)g_hist)[i] = make_uint4(0u, 0u, 0u, 0u);
  if (blockIdx.x == 0 && threadIdx.x < ROWS) g_npred[threadIdx.x] = 0;
}

// ---------------------------------------------------------------- histogram
__global__ void __launch_bounds__(256) k_hist(const float* __restrict__ x,
                                              const void* __restrict__ tgt) {
  const int n = blockIdx.y;
  const int p = (blockIdx.x * 256 + threadIdx.x) * 4;

  // Detect targets dtype: if int32, odd 32-bit words carry real (random 0/1)
  // data -> some nonzero. If int64 (values 0/1), odd words are all zero.
  const int* t32 = (const int*)tgt;
  int probe = t32[2 * threadIdx.x + 1];
  bool is32 = __syncthreads_or(probe != 0);

  long long tv[4];
  if (is32) {
    int4 q = *(const int4*)(t32 + (size_t)n * PP + p);
    tv[0] = q.x; tv[1] = q.y; tv[2] = q.z; tv[3] = q.w;
  } else {
    longlong4 q = *(const longlong4*)((const long long*)tgt + (size_t)n * PP + p);
    tv[0] = q.x; tv[1] = q.y; tv[2] = q.z; tv[3] = q.w;
  }
  float4 v0 = *(const float4*)(x + ((size_t)n * NC + 0) * PP + p);
  float4 v1 = *(const float4*)(x + ((size_t)n * NC + 1) * PP + p);
  float xs0[4] = {v0.x, v0.y, v0.z, v0.w};
  float xs1[4] = {v1.x, v1.y, v1.z, v1.w};

  const unsigned int base0 = (unsigned int)n * BINS;          // row c=0
  const unsigned int base1 = (unsigned int)(NB + n) * BINS;   // row c=1
  int c0 = 0, c1 = 0;
#pragma unroll
  for (int k = 0; k < 4; k++) {
    bool  m0 = (tv[k] == 0);      // mask for class 0; class 1 mask = !m0
    float a0 = xs0[k], a1 = xs1[k];
    c0 += (a0 > 0.25f);
    c1 += (a1 > 0.25f);
    float d0 = m0 ? (1.0f - a0) : a0;    // |mask - x|
    float d1 = m0 ? a1 : (1.0f - a1);
    unsigned int b0 = min((unsigned int)(d0 * 65536.0f), 65535u);
    unsigned int b1 = min((unsigned int)(d1 * 65536.0f), 65535u);
    atomicAdd(&g_hist[base0 + b0], m0 ? 0x10000u : 1u);
    atomicAdd(&g_hist[base1 + b1], m0 ? 1u : 0x10000u);
  }

  // block-reduce the pred-count contributions (2 atomics per block, not per thread)
  int lane = threadIdx.x & 31, w = threadIdx.x >> 5;
#pragma unroll
  for (int off = 16; off; off >>= 1) {
    c0 += __shfl_down_sync(0xffffffffu, c0, off);
    c1 += __shfl_down_sync(0xffffffffu, c1, off);
  }
  __shared__ int s0[8], s1[8];
  if (lane == 0) { s0[w] = c0; s1[w] = c1; }
  __syncthreads();
  if (threadIdx.x == 0) {
    int a = 0, b = 0;
#pragma unroll
    for (int i = 0; i < 8; i++) { a += s0[i]; b += s1[i]; }
    atomicAdd(&g_npred[n], a);
    atomicAdd(&g_npred[NB + n], b);
  }
}

// ---------------------------------------------------------------- per-row scan
// One block per row. Thread t owns SEG bins in DESCENDING bin order.
__global__ void __launch_bounds__(P2T) k_scan() {
  const int r = blockIdx.x;
  const int t = threadIdx.x;
  const unsigned int* __restrict__ h = g_hist + (size_t)r * BINS;
  const int bhi = BINS - 1 - t * SEG;   // highest bin index of my segment

  // pass A: segment sums (m1 count, total count)
  unsigned int s1 = 0, st = 0;
#pragma unroll 8
  for (int k = 0; k < SEG; k++) {
    unsigned int v = h[bhi - k];
    unsigned int h1 = v >> 16;
    s1 += h1;
    st += h1 + (v & 0xffffu);
  }

  // inclusive block scan over packed (s1 | st) — no cross-carry possible
  __shared__ unsigned long long sm[P2T];
  unsigned long long mine = ((unsigned long long)s1 << 32) | (unsigned long long)st;
  sm[t] = mine;
  __syncthreads();
  for (int off = 1; off < P2T; off <<= 1) {
    unsigned long long v = (t >= off) ? sm[t - off] : 0ull;
    __syncthreads();
    sm[t] += v;
    __syncthreads();
  }
  unsigned long long tot  = sm[P2T - 1];
  unsigned long long excl = sm[t] - mine;
  const unsigned int gts = (unsigned int)(tot >> 32);
  unsigned int K1 = (unsigned int)(excl >> 32);
  unsigned int K  = (unsigned int)(excl & 0xffffffffull);

  // iou(K1,K) = 1 - (gts-K1)/(gts+K-K1) ; defined as 0 at K==0
  float iou_prev = (K == 0)
      ? 0.0f
      : 1.0f - __fdividef((float)(gts - K1), (float)(gts + K - K1));

  // pass B: walk segment high->low, accumulate  d_bin * (iou - iou_prev)
  float acc = 0.0f;
  for (int k = 0; k < SEG; k++) {
    unsigned int v = h[bhi - k];
    if (v) {
      unsigned int h1 = v >> 16;
      K1 += h1;
      K  += h1 + (v & 0xffffu);
      float iou = 1.0f - __fdividef((float)(gts - K1), (float)(gts + K - K1));
      float d   = ((float)(bhi - k) + 0.5f) * (1.0f / 65536.0f);
      acc += d * (iou - iou_prev);
      iou_prev = iou;
    }
  }

  // block reduce acc
  __syncthreads();
  float* smf = (float*)sm;
  smf[t] = acc;
  __syncthreads();
  for (int off = P2T / 2; off > 0; off >>= 1) {
    if (t < off) smf[t] += smf[t + off];
    __syncthreads();
  }
  if (t == 0) { g_per[r] = smf[0]; g_gts[r] = gts; }
}

// ---------------------------------------------------------------- finalize
__global__ void k_final(const float* __restrict__ cw,
                        const float* __restrict__ tw,
                        float* __restrict__ out) {
  const int t = threadIdx.x;          // 64 threads, t == row == c*NB + n
  const int c = t >> 5, n = t & 31;
  float cwv   = cw[c];
  bool empty  = (g_gts[t] == 0) && (g_npred[t] == 0);
  bool valid  = (cwv != 0.0f) && !empty;
  float w = valid ? g_per[t] * tw[n] * cwv : 0.0f;
  float v = valid ? 1.0f : 0.0f;
#pragma unroll
  for (int off = 16; off; off >>= 1) {
    w += __shfl_down_sync(0xffffffffu, w, off);
    v += __shfl_down_sync(0xffffffffu, v, off);
  }
  __shared__ float sw[2], sv[2];
  if ((t & 31) == 0) { sw[t >> 5] = w; sv[t >> 5] = v; }
  __syncthreads();
  if (t == 0) {
    float W = sw[0] + sw[1];
    float V = sv[0] + sv[1];
    out[0] = W / (float)NB / V;
  }
}

// ---------------------------------------------------------------- launch
extern "C" void kernel_launch(void* const* d_in, const int* in_sizes, int n_in,
                              void* d_out, int out_size) {
  const float* x   = (const float*)d_in[0];
  const void*  tgt = d_in[1];
  const float* cw  = (const float*)d_in[2];
  const float* tw  = (const float*)d_in[3];
  float* out = (float*)d_out;

  k_zero<<<(int)(((size_t)ROWS * BINS / 4 + 255) / 256), 256>>>();
  dim3 g1(PP / (256 * 4), NB);
  k_hist<<<g1, 256>>>(x, tgt);
  k_scan<<<ROWS, P2T>>>();
  k_final<<<1, 64>>>(cw, tw, out);
}

// round 2
// speedup vs baseline: 4.3050x; 4.3050x over previous
#include <cuda_runtime.h>

#define NB   32
#define NC   2
#define PP   262144            // H*W
#define BINS 4096
#define ROWS (NC * NB)         // 64 rows, row = c*NB + n
#define BPS  4                 // blocks per sample  -> 128 blocks total (1 wave)
#define HT   512               // hist threads per block
#define PXB  (PP / BPS)        // 65536 pixels per block
#define ITERS (PXB / (HT * 4)) // 32 iterations of 4 pixels
#define P2T  1024
#define SEG  (BINS / P2T)      // 4 bins per scan thread

// Scratch (static device globals; no allocation)
__device__ unsigned int g_hist[ROWS * BINS];   // packed: hi16=count(m=1), lo16=count(m=0)
__device__ int          g_npred[ROWS];
__device__ float        g_per[ROWS];
__device__ unsigned int g_gts[ROWS];

// ---------------------------------------------------------------- zero scratch (1 MB)
__global__ void __launch_bounds__(256) k_zero() {
  size_t i = (size_t)blockIdx.x * 256 + threadIdx.x;
  if (i < ((size_t)ROWS * BINS) / 4)
    ((uint4*)g_hist)[i] = make_uint4(0u, 0u, 0u, 0u);
  if (blockIdx.x == 0 && threadIdx.x < ROWS) g_npred[threadIdx.x] = 0;
}

// ---------------------------------------------------------------- histogram
// grid = (BPS, NB). Per-block smem-private 2-class histogram, single global flush.
__global__ void __launch_bounds__(HT) k_hist(const float* __restrict__ x,
                                             const void* __restrict__ tgt) {
  __shared__ unsigned int sh[2 * BINS];   // [0,BINS)=class0, [BINS,2BINS)=class1
  const int n    = blockIdx.y;
  const int tid  = threadIdx.x;
  const int base = blockIdx.x * PXB;

  // zero smem hist
#pragma unroll
  for (int i = tid; i < 2 * BINS; i += HT) sh[i] = 0u;

  // Detect targets dtype: if int32, odd 32-bit words carry real data (values 0/1
  // random) -> some nonzero. If int64 (values 0/1), odd words are all zero.
  const int* t32 = (const int*)tgt;
  int probe = t32[2 * tid + 1];
  bool is32 = __syncthreads_or(probe != 0);   // also the barrier for smem zeroing

  int c0 = 0, c1 = 0;
#pragma unroll 2
  for (int it = 0; it < ITERS; it++) {
    const int p = base + (it * HT + tid) * 4;

    long long tv[4];
    if (is32) {
      int4 q = *(const int4*)(t32 + (size_t)n * PP + p);
      tv[0] = q.x; tv[1] = q.y; tv[2] = q.z; tv[3] = q.w;
    } else {
      longlong4 q = *(const longlong4*)((const long long*)tgt + (size_t)n * PP + p);
      tv[0] = q.x; tv[1] = q.y; tv[2] = q.z; tv[3] = q.w;
    }
    float4 v0 = *(const float4*)(x + ((size_t)n * NC + 0) * PP + p);
    float4 v1 = *(const float4*)(x + ((size_t)n * NC + 1) * PP + p);
    float xs0[4] = {v0.x, v0.y, v0.z, v0.w};
    float xs1[4] = {v1.x, v1.y, v1.z, v1.w};

#pragma unroll
    for (int k = 0; k < 4; k++) {
      bool  m0 = (tv[k] == 0);           // class-0 mask; class-1 mask = !m0
      float a0 = xs0[k], a1 = xs1[k];
      c0 += (a0 > 0.25f);
      c1 += (a1 > 0.25f);
      float d0 = m0 ? (1.0f - a0) : a0;  // |mask - x|
      float d1 = m0 ? a1 : (1.0f - a1);
      unsigned int b0 = min((unsigned int)(d0 * (float)BINS), (unsigned int)(BINS - 1));
      unsigned int b1 = min((unsigned int)(d1 * (float)BINS), (unsigned int)(BINS - 1));
      atomicAdd(&sh[b0],        m0 ? 0x10000u : 1u);
      atomicAdd(&sh[BINS + b1], m0 ? 1u : 0x10000u);
    }
  }
  __syncthreads();

  // flush: 8192 words per block, skip zeros (~1M global REDs total)
  const unsigned int r0 = (unsigned int)n * BINS;          // row c=0
  const unsigned int r1 = (unsigned int)(NB + n) * BINS;   // row c=1
#pragma unroll
  for (int i = tid; i < BINS; i += HT) {
    unsigned int v0s = sh[i];
    if (v0s) atomicAdd(&g_hist[r0 + i], v0s);
    unsigned int v1s = sh[BINS + i];
    if (v1s) atomicAdd(&g_hist[r1 + i], v1s);
  }

  // block-reduce pred counts (2 global atomics per block)
  int lane = tid & 31, w = tid >> 5;
#pragma unroll
  for (int off = 16; off; off >>= 1) {
    c0 += __shfl_down_sync(0xffffffffu, c0, off);
    c1 += __shfl_down_sync(0xffffffffu, c1, off);
  }
  __shared__ int s0[HT / 32], s1[HT / 32];
  if (lane == 0) { s0[w] = c0; s1[w] = c1; }
  __syncthreads();
  if (tid == 0) {
    int a = 0, b = 0;
#pragma unroll
    for (int i = 0; i < HT / 32; i++) { a += s0[i]; b += s1[i]; }
    atomicAdd(&g_npred[n], a);
    atomicAdd(&g_npred[NB + n], b);
  }
}

// ---------------------------------------------------------------- per-row scan
// One block per row. Thread t owns SEG bins in DESCENDING bin order.
__global__ void __launch_bounds__(P2T) k_scan() {
  const int r = blockIdx.x;
  const int t = threadIdx.x;
  const unsigned int* __restrict__ h = g_hist + (size_t)r * BINS;
  const int bhi = BINS - 1 - t * SEG;   // highest bin index of my segment

  // pass A: segment sums (m1 count, total count)
  unsigned int s1 = 0, st = 0;
#pragma unroll
  for (int k = 0; k < SEG; k++) {
    unsigned int v = h[bhi - k];
    unsigned int h1 = v >> 16;
    s1 += h1;
    st += h1 + (v & 0xffffu);
  }

  // inclusive block scan over packed (s1 | st) — no cross-carry possible
  __shared__ unsigned long long sm[P2T];
  unsigned long long mine = ((unsigned long long)s1 << 32) | (unsigned long long)st;
  sm[t] = mine;
  __syncthreads();
  for (int off = 1; off < P2T; off <<= 1) {
    unsigned long long v = (t >= off) ? sm[t - off] : 0ull;
    __syncthreads();
    sm[t] += v;
    __syncthreads();
  }
  unsigned long long tot  = sm[P2T - 1];
  unsigned long long excl = sm[t] - mine;
  const unsigned int gts = (unsigned int)(tot >> 32);
  unsigned int K1 = (unsigned int)(excl >> 32);
  unsigned int K  = (unsigned int)(excl & 0xffffffffull);

  // iou(K1,K) = 1 - (gts-K1)/(gts+K-K1) ; defined as 0 at K==0
  float iou_prev = (K == 0)
      ? 0.0f
      : 1.0f - __fdividef((float)(gts - K1), (float)(gts + K - K1));

  // pass B: walk segment high->low, accumulate  d_bin * (iou - iou_prev)
  float acc = 0.0f;
#pragma unroll
  for (int k = 0; k < SEG; k++) {
    unsigned int v = h[bhi - k];
    if (v) {
      unsigned int h1 = v >> 16;
      K1 += h1;
      K  += h1 + (v & 0xffffu);
      float iou = 1.0f - __fdividef((float)(gts - K1), (float)(gts + K - K1));
      float d   = ((float)(bhi - k) + 0.5f) * (1.0f / (float)BINS);
      acc += d * (iou - iou_prev);
      iou_prev = iou;
    }
  }

  // block reduce acc
  __syncthreads();
  float* smf = (float*)sm;
  smf[t] = acc;
  __syncthreads();
  for (int off = P2T / 2; off > 0; off >>= 1) {
    if (t < off) smf[t] += smf[t + off];
    __syncthreads();
  }
  if (t == 0) { g_per[r] = smf[0]; g_gts[r] = gts; }
}

// ---------------------------------------------------------------- finalize
__global__ void k_final(const float* __restrict__ cw,
                        const float* __restrict__ tw,
                        float* __restrict__ out) {
  const int t = threadIdx.x;          // 64 threads, t == row == c*NB + n
  const int c = t >> 5, n = t & 31;
  float cwv   = cw[c];
  bool empty  = (g_gts[t] == 0) && (g_npred[t] == 0);
  bool valid  = (cwv != 0.0f) && !empty;
  float w = valid ? g_per[t] * tw[n] * cwv : 0.0f;
  float v = valid ? 1.0f : 0.0f;
#pragma unroll
  for (int off = 16; off; off >>= 1) {
    w += __shfl_down_sync(0xffffffffu, w, off);
    v += __shfl_down_sync(0xffffffffu, v, off);
  }
  __shared__ float sw[2], sv[2];
  if ((t & 31) == 0) { sw[t >> 5] = w; sv[t >> 5] = v; }
  __syncthreads();
  if (t == 0) {
    float W = sw[0] + sw[1];
    float V = sv[0] + sv[1];
    out[0] = W / (float)NB / V;
  }
}

// ---------------------------------------------------------------- launch
extern "C" void kernel_launch(void* const* d_in, const int* in_sizes, int n_in,
                              void* d_out, int out_size) {
  const float* x   = (const float*)d_in[0];
  const void*  tgt = d_in[1];
  const float* cw  = (const float*)d_in[2];
  const float* tw  = (const float*)d_in[3];
  float* out = (float*)d_out;

  k_zero<<<(ROWS * BINS / 4 + 255) / 256, 256>>>();
  dim3 g1(BPS, NB);
  k_hist<<<g1, HT>>>(x, tgt);
  k_scan<<<ROWS, P2T>>>();
  k_final<<<1, 64>>>(cw, tw, out);
}